// round 2
// baseline (speedup 1.0000x reference)
#include <cuda_runtime.h>
#include <math.h>

#define NFEAT 500
#define DFULL 128
#define NCAP  8
#define DD    16
#define MNB   32
#define RIT   6
#define CUTN  5
#define NMAX  20000
#define NCLASS 16

// ---- scratch (static device globals; no allocation allowed) ----
__device__ float g_h  [NMAX * DFULL];
__device__ float g_xn0[NMAX * DFULL];
__device__ float g_xn1[NMAX * DFULL];
__device__ float g_u  [NMAX * DFULL];
__device__ float g_T  [NMAX * DD];
__device__ unsigned char g_arg[NMAX * CUTN];
__device__ float g_attn;
__device__ int   g_odd_nonzero;   // 1 -> nb is int32 (stride 1); 0 -> int64 (stride 2)

__device__ __forceinline__ int nb_at(const int* __restrict__ nb32, size_t pos, int st) {
    return nb32[pos * (size_t)st];
}

// =====================================================================
// K0: detect nb dtype. int64 little-endian non-negative -> all odd
// int32 words are zero. int32 random data -> some odd word nonzero.
// =====================================================================
__global__ void k_detect_nb_init() { g_odd_nonzero = 0; g_attn = 0.f; }

__global__ void k_detect_nb(const int* __restrict__ nb32, int n_pairs)
{
    int i = blockIdx.x * blockDim.x + threadIdx.x;
    if (i >= n_pairs) return;
    if (nb32[2 * i + 1] != 0) atomicOr(&g_odd_nonzero, 1);
}

// =====================================================================
// K1: h = x @ pca_w + pca_b   (n x 500) @ (500 x 128)
// BM=64, BN=128, BK=16, 256 threads, 8x4 microtile
// =====================================================================
__global__ void k_gemm_pca(const float* __restrict__ x,
                           const float* __restrict__ W,
                           const float* __restrict__ bias,
                           int n)
{
    __shared__ float As[64][16];
    __shared__ float Bs[16][128];

    int tid = threadIdx.x;
    int ty = tid >> 5;      // 0..7
    int tx = tid & 31;      // 0..31
    int row0 = blockIdx.x * 64;

    float acc[8][4];
#pragma unroll
    for (int r = 0; r < 8; r++)
#pragma unroll
        for (int c = 0; c < 4; c++) acc[r][c] = 0.f;

    for (int kt = 0; kt < NFEAT; kt += 16) {
        // load As (64x16): one float4 per thread
        {
            int r = tid >> 2;
            int q = (tid & 3) * 4;
            int grow = row0 + r;
            int col = kt + q;
            float4 v = make_float4(0.f, 0.f, 0.f, 0.f);
            if (grow < n) {
                if (col + 3 < NFEAT) {
                    v = *(const float4*)(x + (size_t)grow * NFEAT + col);
                } else {
                    float tv[4] = {0.f, 0.f, 0.f, 0.f};
                    for (int i = 0; i < 4; i++)
                        if (col + i < NFEAT) tv[i] = x[(size_t)grow * NFEAT + col + i];
                    v = make_float4(tv[0], tv[1], tv[2], tv[3]);
                }
            }
            As[r][q + 0] = v.x; As[r][q + 1] = v.y;
            As[r][q + 2] = v.z; As[r][q + 3] = v.w;
        }
        // load Bs (16x128): two float4 per thread
#pragma unroll
        for (int i = 0; i < 2; i++) {
            int idx = tid * 2 + i;
            int rr = idx >> 5;        // 0..15
            int cq = (idx & 31) * 4;  // 0..124
            float4 v = make_float4(0.f, 0.f, 0.f, 0.f);
            if (kt + rr < NFEAT)
                v = *(const float4*)(W + (size_t)(kt + rr) * DFULL + cq);
            Bs[rr][cq + 0] = v.x; Bs[rr][cq + 1] = v.y;
            Bs[rr][cq + 2] = v.z; Bs[rr][cq + 3] = v.w;
        }
        __syncthreads();

#pragma unroll
        for (int kk = 0; kk < 16; kk++) {
            float4 b4 = ((float4*)&Bs[kk][0])[tx];
            float bv[4] = {b4.x, b4.y, b4.z, b4.w};
            float av[8];
#pragma unroll
            for (int r = 0; r < 8; r++) av[r] = As[ty * 8 + r][kk];
#pragma unroll
            for (int r = 0; r < 8; r++)
#pragma unroll
                for (int c = 0; c < 4; c++)
                    acc[r][c] = fmaf(av[r], bv[c], acc[r][c]);
        }
        __syncthreads();
    }

    float4 b4 = ((const float4*)bias)[tx];
    float bv[4] = {b4.x, b4.y, b4.z, b4.w};
#pragma unroll
    for (int r = 0; r < 8; r++) {
        int grow = row0 + ty * 8 + r;
        if (grow < n) {
            float4 o = make_float4(acc[r][0] + bv[0], acc[r][1] + bv[1],
                                   acc[r][2] + bv[2], acc[r][3] + bv[3]);
            *(float4*)(g_h + (size_t)grow * DFULL + tx * 4) = o;
        }
    }
}

// =====================================================================
// K2: per-node attention-loss contribution + xn0 = normalize(relu(h))
// one warp per node, 8 warps/block
// =====================================================================
__global__ void k_attn_xn0(const float* __restrict__ ln_g,
                           const float* __restrict__ ln_b,
                           const float* __restrict__ wqs,
                           const float* __restrict__ wks,
                           int n)
{
    __shared__ float sQ[8][128];
    __shared__ float sH[8][128];
    __shared__ float sS[8][64];
    __shared__ float s_wq[256], s_wk[256];
    __shared__ float s_g[16], s_b[16];
    __shared__ float blk_acc;

    int tid = threadIdx.x;
    { s_wq[tid] = wqs[tid]; s_wk[tid] = wks[tid]; }
    if (tid < 16)  { s_g[tid] = ln_g[tid]; s_b[tid] = ln_b[tid]; }
    if (tid == 0)  blk_acc = 0.f;
    __syncthreads();

    int wp = tid >> 5, lane = tid & 31;
    int v = blockIdx.x * 8 + wp;
    if (v < n) {
        int a  = lane >> 2;
        int c0 = (lane & 3) * 4;
        float4 h4 = *(const float4*)(g_h + (size_t)v * DFULL + lane * 4);
        float hv[4] = {h4.x, h4.y, h4.z, h4.w};

        // LayerNorm over the 16-dim capsule (4 lanes per capsule)
        float s1 = hv[0] + hv[1] + hv[2] + hv[3];
        float s2 = hv[0]*hv[0] + hv[1]*hv[1] + hv[2]*hv[2] + hv[3]*hv[3];
        s1 += __shfl_xor_sync(0xffffffffu, s1, 1);
        s1 += __shfl_xor_sync(0xffffffffu, s1, 2);
        s2 += __shfl_xor_sync(0xffffffffu, s2, 1);
        s2 += __shfl_xor_sync(0xffffffffu, s2, 2);
        float mu  = s1 * (1.f / 16.f);
        float var = s2 * (1.f / 16.f) - mu * mu;
        float inv = rsqrtf(var + 1e-6f);
        float qn[4];
#pragma unroll
        for (int i = 0; i < 4; i++)
            qn[i] = (hv[i] - mu) * inv * s_g[c0 + i] + s_b[c0 + i];

#pragma unroll
        for (int i = 0; i < 4; i++) {
            sQ[wp][lane * 4 + i] = qn[i];
            sH[wp][lane * 4 + i] = hv[i];
        }
        __syncwarp();

        float q4[4] = {0.f, 0.f, 0.f, 0.f};
        float k4[4] = {0.f, 0.f, 0.f, 0.f};
#pragma unroll
        for (int j = 0; j < 16; j++) {
            float qa = sQ[wp][a * 16 + j];
            float ha = sH[wp][a * 16 + j];
#pragma unroll
            for (int i = 0; i < 4; i++) {
                q4[i] = fmaf(qa, s_wq[j * 16 + c0 + i], q4[i]);
                k4[i] = fmaf(ha, s_wk[j * 16 + c0 + i], k4[i]);
            }
        }
        __syncwarp();
#pragma unroll
        for (int i = 0; i < 4; i++) {
            sQ[wp][lane * 4 + i] = q4[i];
            sH[wp][lane * 4 + i] = k4[i];
        }
        __syncwarp();

        // scores (8x8), 2 per lane, scaled by 1/temp = 1/4
        float sc[2];
#pragma unroll
        for (int r = 0; r < 2; r++) {
            int id = lane * 2 + r;
            int aa = id >> 3, bb = id & 7;
            float s = 0.f;
#pragma unroll
            for (int c = 0; c < 16; c++)
                s = fmaf(sQ[wp][aa * 16 + c], sH[wp][bb * 16 + c], s);
            sc[r] = s * 0.25f;
        }
        sS[wp][lane * 2 + 0] = sc[0];
        sS[wp][lane * 2 + 1] = sc[1];
        __syncwarp();

        float contrib = 0.f;
        if (lane < 8) {
            float mx = -1e30f;
#pragma unroll
            for (int b = 0; b < 8; b++) mx = fmaxf(mx, sS[wp][lane * 8 + b]);
            float sum = 0.f;
#pragma unroll
            for (int b = 0; b < 8; b++) sum += expf(sS[wp][lane * 8 + b] - mx);
            float diag = expf(sS[wp][lane * 8 + lane] - mx) / sum;
            contrib = 1.f - diag;
        }
        contrib += __shfl_xor_sync(0xffffffffu, contrib, 1);
        contrib += __shfl_xor_sync(0xffffffffu, contrib, 2);
        contrib += __shfl_xor_sync(0xffffffffu, contrib, 4);
        if (lane == 0) atomicAdd(&blk_acc, contrib);

        // xn0 = normalize(relu(h)) per capsule
        float r4[4];
#pragma unroll
        for (int i = 0; i < 4; i++) r4[i] = fmaxf(hv[i], 0.f);
        float ss = r4[0]*r4[0] + r4[1]*r4[1] + r4[2]*r4[2] + r4[3]*r4[3];
        ss += __shfl_xor_sync(0xffffffffu, ss, 1);
        ss += __shfl_xor_sync(0xffffffffu, ss, 2);
        float scale = 1.f / fmaxf(sqrtf(ss), 1e-12f);
        float4 o = make_float4(r4[0]*scale, r4[1]*scale, r4[2]*scale, r4[3]*scale);
        *(float4*)(g_xn0 + (size_t)v * DFULL + lane * 4) = o;
    }
    __syncthreads();
    if (tid == 0) atomicAdd(&g_attn, blk_acc);
}

// =====================================================================
// K3/K4: dynamic routing. One block (256 thr) per node.
// thread t = (m,k): m = t>>3 (neighbor), k = t&7 (capsule). z[16] in regs.
// LAST=false: writes xn_out = normalize(relu(u)).
// LAST=true : writes g_u (raw final u) + argmax capsule for first 5 nbrs.
// =====================================================================
template <bool LAST>
__global__ void k_routing(const float* __restrict__ xn,
                          const int* __restrict__ nb32,
                          float* __restrict__ xn_out,
                          int n)
{
    __shared__ float x3s[128];
    __shared__ float u_s[8 * 17];      // padded stride 17
    __shared__ float part[8][8][16];

    int v = blockIdx.x;
    int t = threadIdx.x;
    int m = t >> 3, k = t & 7;
    int lane = t & 31, wp = t >> 5;
    int st = g_odd_nonzero ? 1 : 2;

    int nbv = nb_at(nb32, (size_t)v * MNB + m, st);
    float z[16];
    if (nbv >= 0) {
        const float4* src = (const float4*)(xn + (size_t)nbv * DFULL + k * DD);
#pragma unroll
        for (int q = 0; q < 4; q++) {
            float4 t4 = src[q];
            z[q * 4 + 0] = t4.x; z[q * 4 + 1] = t4.y;
            z[q * 4 + 2] = t4.z; z[q * 4 + 3] = t4.w;
        }
    } else {
#pragma unroll
        for (int i = 0; i < 16; i++) z[i] = 0.f;
    }
    if (t < 32)
        ((float4*)x3s)[t] = ((const float4*)(xn + (size_t)v * DFULL))[t];
    __syncthreads();

    for (int it = 0; it < RIT; it++) {
        float s = 0.f;
        if (it > 0) {
#pragma unroll
            for (int c = 0; c < 16; c++)
                s = fmaf(z[c], u_s[k * 17 + c], s);
        }

        if (LAST && it == RIT - 1) {
            // argmax over k within 8-lane group (ties -> lowest k)
            float bs = s; int bk = k;
#pragma unroll
            for (int d = 1; d <= 4; d <<= 1) {
                float os = __shfl_xor_sync(0xffffffffu, bs, d);
                int   ok = __shfl_xor_sync(0xffffffffu, bk, d);
                if (os > bs || (os == bs && ok < bk)) { bs = os; bk = ok; }
            }
            if (k == 0 && m < CUTN)
                g_arg[(size_t)v * CUTN + m] = (unsigned char)bk;
        }

        // softmax over k (8-lane groups)
        float mx = s;
        mx = fmaxf(mx, __shfl_xor_sync(0xffffffffu, mx, 1));
        mx = fmaxf(mx, __shfl_xor_sync(0xffffffffu, mx, 2));
        mx = fmaxf(mx, __shfl_xor_sync(0xffffffffu, mx, 4));
        float e = expf(s - mx);
        float sum = e;
        sum += __shfl_xor_sync(0xffffffffu, sum, 1);
        sum += __shfl_xor_sync(0xffffffffu, sum, 2);
        sum += __shfl_xor_sync(0xffffffffu, sum, 4);
        float p = e / sum;

        // weighted sum over m: reduce 4 m's in-warp, stage per-warp partials
#pragma unroll
        for (int c = 0; c < 16; c++) {
            float wv = p * z[c];
            wv += __shfl_xor_sync(0xffffffffu, wv, 8);
            wv += __shfl_xor_sync(0xffffffffu, wv, 16);
            if (lane < 8) part[wp][lane][c] = wv;
        }
        __syncthreads();

        if (t < 128) {
            int k2 = t >> 4, c2 = t & 15;
            float nu = x3s[t];
#pragma unroll
            for (int w8 = 0; w8 < 8; w8++) nu += part[w8][k2][c2];
            if (it < RIT - 1) {
                float ss = nu * nu;
                ss += __shfl_xor_sync(0xffffffffu, ss, 1);
                ss += __shfl_xor_sync(0xffffffffu, ss, 2);
                ss += __shfl_xor_sync(0xffffffffu, ss, 4);
                ss += __shfl_xor_sync(0xffffffffu, ss, 8);
                float scale = 1.f / fmaxf(sqrtf(ss), 1e-12f);
                nu *= scale;
            }
            u_s[k2 * 17 + c2] = nu;
        }
        __syncthreads();
    }

    if (t < 128) {
        int k2 = t >> 4, c2 = t & 15;
        float uu = u_s[k2 * 17 + c2];
        if (LAST) {
            g_u[(size_t)v * DFULL + t] = uu;
        } else {
            float r = fmaxf(uu, 0.f);
            float ss = r * r;
            ss += __shfl_xor_sync(0xffffffffu, ss, 1);
            ss += __shfl_xor_sync(0xffffffffu, ss, 2);
            ss += __shfl_xor_sync(0xffffffffu, ss, 4);
            ss += __shfl_xor_sync(0xffffffffu, ss, 8);
            float scale = 1.f / fmaxf(sqrtf(ss), 1e-12f);
            xn_out[(size_t)v * DFULL + t] = r * scale;
        }
    }
}

// =====================================================================
// K5: T[w,:] = sum_{j<5} xn1[nb[w,j], arg[w,j], :]
// =====================================================================
__global__ void k_compute_T(const int* __restrict__ nb32, int n)
{
    int tid = blockIdx.x * blockDim.x + threadIdx.x;
    if (tid >= n * DD) return;
    int w = tid >> 4, c = tid & 15;
    int st = g_odd_nonzero ? 1 : 2;
    float s = 0.f;
#pragma unroll
    for (int j = 0; j < CUTN; j++) {
        int nv = nb_at(nb32, (size_t)w * MNB + j, st);
        if (nv >= 0) {
            int a = g_arg[(size_t)w * CUTN + j];
            s += g_xn1[(size_t)nv * DFULL + a * DD + c];
        }
    }
    g_T[tid] = s;
}

// =====================================================================
// K6: meta = u + (1/25) * two-hop aggregate; logits = relu(meta) @ mlp_w + b;
//     write log_softmax, attn_loss scalar, and logits (meta output).
// One warp per node.
// =====================================================================
__global__ void k_meta_out(const int* __restrict__ nb32,
                           const float* __restrict__ mlp_w,
                           const float* __restrict__ mlp_b,
                           float* __restrict__ out,
                           int n)
{
    __shared__ float s_w[128 * 16];
    __shared__ float s_b[16];
    __shared__ float sM[8][128];

    int tid = threadIdx.x;
    for (int i = tid; i < 2048; i += 256) s_w[i] = mlp_w[i];
    if (tid < 16) s_b[tid] = mlp_b[tid];
    __syncthreads();

    int st = g_odd_nonzero ? 1 : 2;
    int wp = tid >> 5, lane = tid & 31;
    int v = blockIdx.x * 8 + wp;
    if (v < n) {
        int a = lane >> 2;
        float4 acc = *(const float4*)(g_u + (size_t)v * DFULL + lane * 4);
        const float inv25 = 1.f / 25.f;
#pragma unroll
        for (int j = 0; j < CUTN; j++) {
            int nv = nb_at(nb32, (size_t)v * MNB + j, st);
            if (nv >= 0) {
                int aj = g_arg[(size_t)v * CUTN + j];
                if (aj == a) {
                    float4 t4 = *(const float4*)(g_T + (size_t)nv * DD + (lane & 3) * 4);
                    acc.x = fmaf(inv25, t4.x, acc.x);
                    acc.y = fmaf(inv25, t4.y, acc.y);
                    acc.z = fmaf(inv25, t4.z, acc.z);
                    acc.w = fmaf(inv25, t4.w, acc.w);
                }
            }
        }
        // relu(meta)
        acc.x = fmaxf(acc.x, 0.f); acc.y = fmaxf(acc.y, 0.f);
        acc.z = fmaxf(acc.z, 0.f); acc.w = fmaxf(acc.w, 0.f);
        *(float4*)&sM[wp][lane * 4] = acc;
        __syncwarp();

        float logit = 0.f;
        if (lane < 16) {
            logit = s_b[lane];
            for (int f = 0; f < 128; f++)
                logit = fmaf(sM[wp][f], s_w[f * 16 + lane], logit);
            out[(size_t)n * 16 + 1 + (size_t)v * 16 + lane] = logit;
        }
        // log_softmax over 16 lanes
        float mx = (lane < 16) ? logit : -1e30f;
        mx = fmaxf(mx, __shfl_xor_sync(0xffffffffu, mx, 1));
        mx = fmaxf(mx, __shfl_xor_sync(0xffffffffu, mx, 2));
        mx = fmaxf(mx, __shfl_xor_sync(0xffffffffu, mx, 4));
        mx = fmaxf(mx, __shfl_xor_sync(0xffffffffu, mx, 8));
        float e = (lane < 16) ? expf(logit - mx) : 0.f;
        float sum = e;
        sum += __shfl_xor_sync(0xffffffffu, sum, 1);
        sum += __shfl_xor_sync(0xffffffffu, sum, 2);
        sum += __shfl_xor_sync(0xffffffffu, sum, 4);
        sum += __shfl_xor_sync(0xffffffffu, sum, 8);
        if (lane < 16)
            out[(size_t)v * 16 + lane] = (logit - mx) - logf(sum);
    }
    if (blockIdx.x == 0 && tid == 0)
        out[(size_t)n * 16] = g_attn / (56.f * (float)n);
}

// =====================================================================
extern "C" void kernel_launch(void* const* d_in, const int* in_sizes, int n_in,
                              void* d_out, int out_size)
{
    const float* x     = (const float*)d_in[0];
    const int*   nb32  = (const int*)d_in[1];
    const float* pca_w = (const float*)d_in[2];
    const float* pca_b = (const float*)d_in[3];
    const float* ln_g  = (const float*)d_in[4];
    const float* ln_b  = (const float*)d_in[5];
    const float* w_qs  = (const float*)d_in[6];
    const float* w_ks  = (const float*)d_in[7];
    const float* mlp_w = (const float*)d_in[8];
    const float* mlp_b = (const float*)d_in[9];
    float* out = (float*)d_out;

    int n = in_sizes[0] / NFEAT;   // 20000
    int n_nb = in_sizes[1];        // n * 32 elements (either dtype)

    float* p_xn0; cudaGetSymbolAddress((void**)&p_xn0, g_xn0);
    float* p_xn1; cudaGetSymbolAddress((void**)&p_xn1, g_xn1);

    k_detect_nb_init<<<1, 1>>>();
    k_detect_nb<<<(n_nb / 2 + 255) / 256, 256>>>(nb32, n_nb / 2);
    k_gemm_pca<<<(n + 63) / 64, 256>>>(x, pca_w, pca_b, n);
    k_attn_xn0<<<(n + 7) / 8, 256>>>(ln_g, ln_b, w_qs, w_ks, n);
    k_routing<false><<<n, 256>>>(p_xn0, nb32, p_xn1, n);
    k_routing<true ><<<n, 256>>>(p_xn1, nb32, nullptr, n);
    k_compute_T<<<(n * DD + 255) / 256, 256>>>(nb32, n);
    k_meta_out<<<(n + 7) / 8, 256>>>(nb32, mlp_w, mlp_b, out, n);
}

// round 3
// speedup vs baseline: 1.8116x; 1.8116x over previous
#include <cuda_runtime.h>
#include <math.h>

#define NFEAT 500
#define DFULL 128
#define NCAP  8
#define DD    16
#define MNB   32
#define RIT   6
#define CUTN  5
#define NMAX  20000
#define NCLASS 16

// ---- scratch (static device globals; no allocation allowed) ----
__device__ float g_h  [NMAX * DFULL];
__device__ float g_xn0[NMAX * DFULL];
__device__ float g_xn1[NMAX * DFULL];
__device__ float g_u  [NMAX * DFULL];
__device__ float g_T  [NMAX * DD];
__device__ unsigned char g_arg[NMAX * CUTN];
__device__ float g_attn;
__device__ int   g_odd_nonzero;   // 1 -> nb is int32 (stride 1); 0 -> int64 (stride 2)

__device__ __forceinline__ int nb_at(const int* __restrict__ nb32, size_t pos, int st) {
    return nb32[pos * (size_t)st];
}

// =====================================================================
// K0: detect nb dtype. int64 little-endian non-negative -> all odd
// int32 words are zero. int32 random data -> some odd word nonzero.
// =====================================================================
__global__ void k_detect_nb_init() { g_odd_nonzero = 0; g_attn = 0.f; }

__global__ void k_detect_nb(const int* __restrict__ nb32, int n_pairs)
{
    int i = blockIdx.x * blockDim.x + threadIdx.x;
    if (i >= n_pairs) return;
    if (nb32[2 * i + 1] != 0) atomicOr(&g_odd_nonzero, 1);
}

// =====================================================================
// K1: h = x @ pca_w + pca_b   (n x 500) @ (500 x 128)
// BM=128, BN=128, BK=16, 256 threads, 8x8 microtile. 157 blocks = 1 wave.
// =====================================================================
__global__ void __launch_bounds__(256, 1)
k_gemm_pca(const float* __restrict__ x,
           const float* __restrict__ W,
           const float* __restrict__ bias,
           int n)
{
    __shared__ float As[16][128];   // transposed: As[k][m]
    __shared__ float Bs[16][128];

    int tid = threadIdx.x;
    int tx = tid & 15;      // n-dir: 8 cols at tx*8
    int ty = tid >> 4;      // m-dir: 8 rows at ty*8
    int row0 = blockIdx.x * 128;

    float acc[8][8];
#pragma unroll
    for (int r = 0; r < 8; r++)
#pragma unroll
        for (int c = 0; c < 8; c++) acc[r][c] = 0.f;

    for (int kt = 0; kt < NFEAT; kt += 16) {
        // load A tile (128 rows x 16 cols), transpose into As[k][m]
#pragma unroll
        for (int i = 0; i < 2; i++) {
            int idx = tid * 2 + i;          // 0..511
            int r = idx >> 2;               // 0..127
            int q = (idx & 3) * 4;          // 0,4,8,12
            int grow = row0 + r;
            int col = kt + q;
            float4 v = make_float4(0.f, 0.f, 0.f, 0.f);
            if (grow < n && col + 3 < NFEAT)
                v = *(const float4*)(x + (size_t)grow * NFEAT + col);
            As[q + 0][r] = v.x; As[q + 1][r] = v.y;
            As[q + 2][r] = v.z; As[q + 3][r] = v.w;
        }
        // load B tile (16 x 128)
#pragma unroll
        for (int i = 0; i < 2; i++) {
            int idx = tid * 2 + i;
            int rr = idx >> 5;              // 0..15
            int cq = (idx & 31) * 4;        // 0..124
            float4 v = make_float4(0.f, 0.f, 0.f, 0.f);
            if (kt + rr < NFEAT)
                v = *(const float4*)(W + (size_t)(kt + rr) * DFULL + cq);
            *(float4*)&Bs[rr][cq] = v;
        }
        __syncthreads();

#pragma unroll
        for (int kk = 0; kk < 16; kk++) {
            float4 a0 = *(float4*)&As[kk][ty * 8];
            float4 a1 = *(float4*)&As[kk][ty * 8 + 4];
            float4 b0 = *(float4*)&Bs[kk][tx * 8];
            float4 b1 = *(float4*)&Bs[kk][tx * 8 + 4];
            float av[8] = {a0.x, a0.y, a0.z, a0.w, a1.x, a1.y, a1.z, a1.w};
            float bv[8] = {b0.x, b0.y, b0.z, b0.w, b1.x, b1.y, b1.z, b1.w};
#pragma unroll
            for (int r = 0; r < 8; r++)
#pragma unroll
                for (int c = 0; c < 8; c++)
                    acc[r][c] = fmaf(av[r], bv[c], acc[r][c]);
        }
        __syncthreads();
    }

    float bvv[8];
#pragma unroll
    for (int c = 0; c < 8; c++) bvv[c] = bias[tx * 8 + c];
#pragma unroll
    for (int r = 0; r < 8; r++) {
        int grow = row0 + ty * 8 + r;
        if (grow < n) {
            float4 o0 = make_float4(acc[r][0] + bvv[0], acc[r][1] + bvv[1],
                                    acc[r][2] + bvv[2], acc[r][3] + bvv[3]);
            float4 o1 = make_float4(acc[r][4] + bvv[4], acc[r][5] + bvv[5],
                                    acc[r][6] + bvv[6], acc[r][7] + bvv[7]);
            *(float4*)(g_h + (size_t)grow * DFULL + tx * 8)     = o0;
            *(float4*)(g_h + (size_t)grow * DFULL + tx * 8 + 4) = o1;
        }
    }
}

// =====================================================================
// K2: per-node attention-loss contribution + xn0 = normalize(relu(h))
// one warp per node, 8 warps/block
// =====================================================================
__global__ void k_attn_xn0(const float* __restrict__ ln_g,
                           const float* __restrict__ ln_b,
                           const float* __restrict__ wqs,
                           const float* __restrict__ wks,
                           int n)
{
    __shared__ float sQ[8][128];
    __shared__ float sH[8][128];
    __shared__ float sS[8][64];
    __shared__ float s_wq[256], s_wk[256];
    __shared__ float s_g[16], s_b[16];
    __shared__ float blk_acc;

    int tid = threadIdx.x;
    { s_wq[tid] = wqs[tid]; s_wk[tid] = wks[tid]; }
    if (tid < 16)  { s_g[tid] = ln_g[tid]; s_b[tid] = ln_b[tid]; }
    if (tid == 0)  blk_acc = 0.f;
    __syncthreads();

    int wp = tid >> 5, lane = tid & 31;
    int v = blockIdx.x * 8 + wp;
    if (v < n) {
        int a  = lane >> 2;
        int c0 = (lane & 3) * 4;
        float4 h4 = *(const float4*)(g_h + (size_t)v * DFULL + lane * 4);
        float hv[4] = {h4.x, h4.y, h4.z, h4.w};

        float s1 = hv[0] + hv[1] + hv[2] + hv[3];
        float s2 = hv[0]*hv[0] + hv[1]*hv[1] + hv[2]*hv[2] + hv[3]*hv[3];
        s1 += __shfl_xor_sync(0xffffffffu, s1, 1);
        s1 += __shfl_xor_sync(0xffffffffu, s1, 2);
        s2 += __shfl_xor_sync(0xffffffffu, s2, 1);
        s2 += __shfl_xor_sync(0xffffffffu, s2, 2);
        float mu  = s1 * (1.f / 16.f);
        float var = s2 * (1.f / 16.f) - mu * mu;
        float inv = rsqrtf(var + 1e-6f);
        float qn[4];
#pragma unroll
        for (int i = 0; i < 4; i++)
            qn[i] = (hv[i] - mu) * inv * s_g[c0 + i] + s_b[c0 + i];

#pragma unroll
        for (int i = 0; i < 4; i++) {
            sQ[wp][lane * 4 + i] = qn[i];
            sH[wp][lane * 4 + i] = hv[i];
        }
        __syncwarp();

        float q4[4] = {0.f, 0.f, 0.f, 0.f};
        float k4[4] = {0.f, 0.f, 0.f, 0.f};
#pragma unroll
        for (int j = 0; j < 16; j++) {
            float qa = sQ[wp][a * 16 + j];
            float ha = sH[wp][a * 16 + j];
#pragma unroll
            for (int i = 0; i < 4; i++) {
                q4[i] = fmaf(qa, s_wq[j * 16 + c0 + i], q4[i]);
                k4[i] = fmaf(ha, s_wk[j * 16 + c0 + i], k4[i]);
            }
        }
        __syncwarp();
#pragma unroll
        for (int i = 0; i < 4; i++) {
            sQ[wp][lane * 4 + i] = q4[i];
            sH[wp][lane * 4 + i] = k4[i];
        }
        __syncwarp();

        float sc[2];
#pragma unroll
        for (int r = 0; r < 2; r++) {
            int id = lane * 2 + r;
            int aa = id >> 3, bb = id & 7;
            float s = 0.f;
#pragma unroll
            for (int c = 0; c < 16; c++)
                s = fmaf(sQ[wp][aa * 16 + c], sH[wp][bb * 16 + c], s);
            sc[r] = s * 0.25f;
        }
        sS[wp][lane * 2 + 0] = sc[0];
        sS[wp][lane * 2 + 1] = sc[1];
        __syncwarp();

        float contrib = 0.f;
        if (lane < 8) {
            float mx = -1e30f;
#pragma unroll
            for (int b = 0; b < 8; b++) mx = fmaxf(mx, sS[wp][lane * 8 + b]);
            float sum = 0.f;
#pragma unroll
            for (int b = 0; b < 8; b++) sum += expf(sS[wp][lane * 8 + b] - mx);
            float diag = expf(sS[wp][lane * 8 + lane] - mx) / sum;
            contrib = 1.f - diag;
        }
        contrib += __shfl_xor_sync(0xffffffffu, contrib, 1);
        contrib += __shfl_xor_sync(0xffffffffu, contrib, 2);
        contrib += __shfl_xor_sync(0xffffffffu, contrib, 4);
        if (lane == 0) atomicAdd(&blk_acc, contrib);

        float r4[4];
#pragma unroll
        for (int i = 0; i < 4; i++) r4[i] = fmaxf(hv[i], 0.f);
        float ss = r4[0]*r4[0] + r4[1]*r4[1] + r4[2]*r4[2] + r4[3]*r4[3];
        ss += __shfl_xor_sync(0xffffffffu, ss, 1);
        ss += __shfl_xor_sync(0xffffffffu, ss, 2);
        float scale = 1.f / fmaxf(sqrtf(ss), 1e-12f);
        float4 o = make_float4(r4[0]*scale, r4[1]*scale, r4[2]*scale, r4[3]*scale);
        *(float4*)(g_xn0 + (size_t)v * DFULL + lane * 4) = o;
    }
    __syncthreads();
    if (tid == 0) atomicAdd(&g_attn, blk_acc);
}

// =====================================================================
// K3/K4: dynamic routing. 4 nodes per 256-thr block, 2 warps (64 thr)
// per node. Lane = g*8+k; each lane holds z for 4 neighbors
// m = w*16 + mm*4 + g, capsule k slice (16 floats each) in registers.
// Softmax over k needs no max-subtract: |z|,|u| rows are unit -> |s|<=1.
// =====================================================================
template <bool LAST>
__global__ void __launch_bounds__(256)
k_routing(const float* __restrict__ xn,
          const int* __restrict__ nb32,
          float* __restrict__ xn_out,
          int n)
{
    __shared__ float x3s [4][128];
    __shared__ float u_s [4][128];
    __shared__ float part[4][2][8][16];

    int t = threadIdx.x;
    int node = t >> 6;
    int l = t & 63;
    int w = (t >> 5) & 1;
    int lane = t & 31;
    int g = lane >> 3;
    int k = lane & 7;

    int v = blockIdx.x * 4 + node;
    bool valid = v < n;
    int vv = valid ? v : (n - 1);
    int st = g_odd_nonzero ? 1 : 2;

    if (l < 32)
        ((float4*)x3s[node])[l] = ((const float4*)(xn + (size_t)vv * DFULL))[l];

    // gather z[4][16]
    float z[4][16];
#pragma unroll
    for (int mm = 0; mm < 4; mm++) {
        int m = w * 16 + mm * 4 + g;
        int nbv = nb_at(nb32, (size_t)vv * MNB + m, st);
        if (nbv >= 0) {
            const float4* src = (const float4*)(xn + (size_t)nbv * DFULL + k * DD);
#pragma unroll
            for (int q = 0; q < 4; q++) {
                float4 t4 = src[q];
                z[mm][q*4+0] = t4.x; z[mm][q*4+1] = t4.y;
                z[mm][q*4+2] = t4.z; z[mm][q*4+3] = t4.w;
            }
        } else {
#pragma unroll
            for (int i = 0; i < 16; i++) z[mm][i] = 0.f;
        }
    }
    __syncthreads();

    int kk2 = l >> 3;          // phase-2 row (0..7)
    int c0  = (l & 7) * 2;     // phase-2 col pair

    for (int it = 0; it < RIT; it++) {
        float acc[16];
        if (it == 0) {
            // p == 1/8 uniformly
#pragma unroll
            for (int c = 0; c < 16; c++)
                acc[c] = (z[0][c] + z[1][c] + z[2][c] + z[3][c]) * 0.125f;
        } else {
            // s[mm] = z[mm] . u[k]
            float4 u0 = *(float4*)&u_s[node][k * 16];
            float4 u1 = *(float4*)&u_s[node][k * 16 + 4];
            float4 u2 = *(float4*)&u_s[node][k * 16 + 8];
            float4 u3 = *(float4*)&u_s[node][k * 16 + 12];
            float ur[16] = {u0.x,u0.y,u0.z,u0.w, u1.x,u1.y,u1.z,u1.w,
                            u2.x,u2.y,u2.z,u2.w, u3.x,u3.y,u3.z,u3.w};
            float s[4];
#pragma unroll
            for (int mm = 0; mm < 4; mm++) {
                float acc0 = 0.f, acc1 = 0.f;
#pragma unroll
                for (int c = 0; c < 16; c += 2) {
                    acc0 = fmaf(z[mm][c],   ur[c],   acc0);
                    acc1 = fmaf(z[mm][c+1], ur[c+1], acc1);
                }
                s[mm] = acc0 + acc1;
            }

            if (LAST && it == RIT - 1) {
                // argmax over k for m < CUT (only warp 0, mm 0/1 needed)
                if (w == 0) {
#pragma unroll
                    for (int mm = 0; mm < 2; mm++) {
                        float bs = s[mm]; int bk = k;
#pragma unroll
                        for (int d = 1; d <= 4; d <<= 1) {
                            float os = __shfl_xor_sync(0xffffffffu, bs, d);
                            int   ok = __shfl_xor_sync(0xffffffffu, bk, d);
                            if (os > bs || (os == bs && ok < bk)) { bs = os; bk = ok; }
                        }
                        int m = mm * 4 + g;
                        if (k == 0 && m < CUTN && valid)
                            g_arg[(size_t)v * CUTN + m] = (unsigned char)bk;
                    }
                }
            }

            // softmax over k (8-lane groups); |s|<=1 so no max-subtract
            float p[4];
#pragma unroll
            for (int mm = 0; mm < 4; mm++) {
                float e = __expf(s[mm]);
                float sum = e;
                sum += __shfl_xor_sync(0xffffffffu, sum, 1);
                sum += __shfl_xor_sync(0xffffffffu, sum, 2);
                sum += __shfl_xor_sync(0xffffffffu, sum, 4);
                p[mm] = e / sum;
            }
#pragma unroll
            for (int c = 0; c < 16; c++)
                acc[c] = fmaf(p[0], z[0][c],
                         fmaf(p[1], z[1][c],
                         fmaf(p[2], z[2][c], p[3] * z[3][c])));
        }

        // reduce over g within warp (xor 8, 16)
#pragma unroll
        for (int c = 0; c < 16; c++) {
            acc[c] += __shfl_xor_sync(0xffffffffu, acc[c], 8);
            acc[c] += __shfl_xor_sync(0xffffffffu, acc[c], 16);
        }
        // lane (g,k) stores its c-quad of the warp partial
        *(float4*)&part[node][w][k][g * 4] =
            make_float4(acc[g*4], acc[g*4+1], acc[g*4+2], acc[g*4+3]);
        __syncthreads();

        // phase 2: u[k][c] = x3 + part0 + part1 (+ normalize)
        {
            float nu0 = x3s[node][kk2*16 + c0]     + part[node][0][kk2][c0]
                        + part[node][1][kk2][c0];
            float nu1 = x3s[node][kk2*16 + c0 + 1] + part[node][0][kk2][c0+1]
                        + part[node][1][kk2][c0+1];
            if (it < RIT - 1) {
                float ss = nu0*nu0 + nu1*nu1;
                ss += __shfl_xor_sync(0xffffffffu, ss, 1);
                ss += __shfl_xor_sync(0xffffffffu, ss, 2);
                ss += __shfl_xor_sync(0xffffffffu, ss, 4);
                float scale = 1.f / fmaxf(sqrtf(ss), 1e-12f);
                nu0 *= scale; nu1 *= scale;
                u_s[node][kk2*16 + c0]     = nu0;
                u_s[node][kk2*16 + c0 + 1] = nu1;
            } else {
                // final u: write outputs
                if (valid) {
                    if (LAST) {
                        g_u[(size_t)v * DFULL + kk2*16 + c0]     = nu0;
                        g_u[(size_t)v * DFULL + kk2*16 + c0 + 1] = nu1;
                    } else {
                        float r0 = fmaxf(nu0, 0.f), r1 = fmaxf(nu1, 0.f);
                        float ss = r0*r0 + r1*r1;
                        ss += __shfl_xor_sync(0xffffffffu, ss, 1);
                        ss += __shfl_xor_sync(0xffffffffu, ss, 2);
                        ss += __shfl_xor_sync(0xffffffffu, ss, 4);
                        float scale = 1.f / fmaxf(sqrtf(ss), 1e-12f);
                        xn_out[(size_t)v * DFULL + kk2*16 + c0]     = r0 * scale;
                        xn_out[(size_t)v * DFULL + kk2*16 + c0 + 1] = r1 * scale;
                    }
                } else {
                    // keep shuffle convergence for invalid nodes
                    float ss = 0.f;
                    ss += __shfl_xor_sync(0xffffffffu, ss, 1);
                    ss += __shfl_xor_sync(0xffffffffu, ss, 2);
                    ss += __shfl_xor_sync(0xffffffffu, ss, 4);
                }
            }
        }
        __syncthreads();
    }
}

// =====================================================================
// K5: T[w,:] = sum_{j<5} xn1[nb[w,j], arg[w,j], :]
// =====================================================================
__global__ void k_compute_T(const int* __restrict__ nb32, int n)
{
    int tid = blockIdx.x * blockDim.x + threadIdx.x;
    if (tid >= n * DD) return;
    int w = tid >> 4, c = tid & 15;
    int st = g_odd_nonzero ? 1 : 2;
    float s = 0.f;
#pragma unroll
    for (int j = 0; j < CUTN; j++) {
        int nv = nb_at(nb32, (size_t)w * MNB + j, st);
        if (nv >= 0) {
            int a = g_arg[(size_t)w * CUTN + j];
            s += g_xn1[(size_t)nv * DFULL + a * DD + c];
        }
    }
    g_T[tid] = s;
}

// =====================================================================
// K6: meta = u + (1/25) * two-hop aggregate; logits = relu(meta) @ mlp_w + b;
//     write log_softmax, attn_loss scalar, and logits (meta output).
// =====================================================================
__global__ void k_meta_out(const int* __restrict__ nb32,
                           const float* __restrict__ mlp_w,
                           const float* __restrict__ mlp_b,
                           float* __restrict__ out,
                           int n)
{
    __shared__ float s_w[128 * 16];
    __shared__ float s_b[16];
    __shared__ float sM[8][128];

    int tid = threadIdx.x;
    for (int i = tid; i < 2048; i += 256) s_w[i] = mlp_w[i];
    if (tid < 16) s_b[tid] = mlp_b[tid];
    __syncthreads();

    int st = g_odd_nonzero ? 1 : 2;
    int wp = tid >> 5, lane = tid & 31;
    int v = blockIdx.x * 8 + wp;
    if (v < n) {
        int a = lane >> 2;
        float4 acc = *(const float4*)(g_u + (size_t)v * DFULL + lane * 4);
        const float inv25 = 1.f / 25.f;
#pragma unroll
        for (int j = 0; j < CUTN; j++) {
            int nv = nb_at(nb32, (size_t)v * MNB + j, st);
            if (nv >= 0) {
                int aj = g_arg[(size_t)v * CUTN + j];
                if (aj == a) {
                    float4 t4 = *(const float4*)(g_T + (size_t)nv * DD + (lane & 3) * 4);
                    acc.x = fmaf(inv25, t4.x, acc.x);
                    acc.y = fmaf(inv25, t4.y, acc.y);
                    acc.z = fmaf(inv25, t4.z, acc.z);
                    acc.w = fmaf(inv25, t4.w, acc.w);
                }
            }
        }
        acc.x = fmaxf(acc.x, 0.f); acc.y = fmaxf(acc.y, 0.f);
        acc.z = fmaxf(acc.z, 0.f); acc.w = fmaxf(acc.w, 0.f);
        *(float4*)&sM[wp][lane * 4] = acc;
        __syncwarp();

        float logit = 0.f;
        if (lane < 16) {
            logit = s_b[lane];
            for (int f = 0; f < 128; f++)
                logit = fmaf(sM[wp][f], s_w[f * 16 + lane], logit);
            out[(size_t)n * 16 + 1 + (size_t)v * 16 + lane] = logit;
        }
        float mx = (lane < 16) ? logit : -1e30f;
        mx = fmaxf(mx, __shfl_xor_sync(0xffffffffu, mx, 1));
        mx = fmaxf(mx, __shfl_xor_sync(0xffffffffu, mx, 2));
        mx = fmaxf(mx, __shfl_xor_sync(0xffffffffu, mx, 4));
        mx = fmaxf(mx, __shfl_xor_sync(0xffffffffu, mx, 8));
        float e = (lane < 16) ? expf(logit - mx) : 0.f;
        float sum = e;
        sum += __shfl_xor_sync(0xffffffffu, sum, 1);
        sum += __shfl_xor_sync(0xffffffffu, sum, 2);
        sum += __shfl_xor_sync(0xffffffffu, sum, 4);
        sum += __shfl_xor_sync(0xffffffffu, sum, 8);
        if (lane < 16)
            out[(size_t)v * 16 + lane] = (logit - mx) - logf(sum);
    }
    if (blockIdx.x == 0 && tid == 0)
        out[(size_t)n * 16] = g_attn / (56.f * (float)n);
}

// =====================================================================
extern "C" void kernel_launch(void* const* d_in, const int* in_sizes, int n_in,
                              void* d_out, int out_size)
{
    const float* x     = (const float*)d_in[0];
    const int*   nb32  = (const int*)d_in[1];
    const float* pca_w = (const float*)d_in[2];
    const float* pca_b = (const float*)d_in[3];
    const float* ln_g  = (const float*)d_in[4];
    const float* ln_b  = (const float*)d_in[5];
    const float* w_qs  = (const float*)d_in[6];
    const float* w_ks  = (const float*)d_in[7];
    const float* mlp_w = (const float*)d_in[8];
    const float* mlp_b = (const float*)d_in[9];
    float* out = (float*)d_out;

    int n = in_sizes[0] / NFEAT;   // 20000
    int n_nb = in_sizes[1];

    float* p_xn0; cudaGetSymbolAddress((void**)&p_xn0, g_xn0);
    float* p_xn1; cudaGetSymbolAddress((void**)&p_xn1, g_xn1);

    k_detect_nb_init<<<1, 1>>>();
    k_detect_nb<<<(n_nb / 2 + 255) / 256, 256>>>(nb32, n_nb / 2);
    k_gemm_pca<<<(n + 127) / 128, 256>>>(x, pca_w, pca_b, n);
    k_attn_xn0<<<(n + 7) / 8, 256>>>(ln_g, ln_b, w_qs, w_ks, n);
    k_routing<false><<<(n + 3) / 4, 256>>>(p_xn0, nb32, p_xn1, n);
    k_routing<true ><<<(n + 3) / 4, 256>>>(p_xn1, nb32, nullptr, n);
    k_compute_T<<<(n * DD + 255) / 256, 256>>>(nb32, n);
    k_meta_out<<<(n + 7) / 8, 256>>>(nb32, mlp_w, mlp_b, out, n);
}

// round 4
// speedup vs baseline: 1.8730x; 1.0339x over previous
#include <cuda_runtime.h>
#include <math.h>

#define NFEAT 500
#define DFULL 128
#define NCAP  8
#define DD    16
#define MNB   32
#define RIT   6
#define CUTN  5
#define NMAX  20000
#define NCLASS 16

typedef unsigned long long u64;

// ---- packed f32x2 helpers (sm_100+) ----
__device__ __forceinline__ u64 pack2(float lo, float hi) {
    u64 r; asm("mov.b64 %0, {%1, %2};" : "=l"(r) : "f"(lo), "f"(hi)); return r;
}
__device__ __forceinline__ void unpack2(u64 v, float& lo, float& hi) {
    asm("mov.b64 {%0, %1}, %2;" : "=f"(lo), "=f"(hi) : "l"(v));
}
__device__ __forceinline__ u64 fma2(u64 a, u64 b, u64 c) {
    u64 d; asm("fma.rn.f32x2 %0, %1, %2, %3;" : "=l"(d) : "l"(a), "l"(b), "l"(c)); return d;
}
__device__ __forceinline__ u64 add2(u64 a, u64 b) {
    u64 d; asm("add.rn.f32x2 %0, %1, %2;" : "=l"(d) : "l"(a), "l"(b)); return d;
}
__device__ __forceinline__ u64 mul2(u64 a, u64 b) {
    u64 d; asm("mul.rn.f32x2 %0, %1, %2;" : "=l"(d) : "l"(a), "l"(b)); return d;
}

// ---- scratch (static device globals; no allocation allowed) ----
__device__ float g_h  [NMAX * DFULL];
__device__ float g_xn0[NMAX * DFULL];
__device__ float g_xn1[NMAX * DFULL];
__device__ float g_u  [NMAX * DFULL];
__device__ float g_T  [NMAX * DD];
__device__ unsigned char g_arg[NMAX * CUTN];
__device__ float g_attn;
__device__ int   g_odd_nonzero;   // 1 -> nb is int32 (stride 1); 0 -> int64 (stride 2)

__device__ __forceinline__ int nb_at(const int* __restrict__ nb32, size_t pos, int st) {
    return nb32[pos * (size_t)st];
}

// =====================================================================
// K0: detect nb dtype.
// =====================================================================
__global__ void k_detect_nb_init() { g_odd_nonzero = 0; g_attn = 0.f; }

__global__ void k_detect_nb(const int* __restrict__ nb32, int n_pairs)
{
    int i = blockIdx.x * blockDim.x + threadIdx.x;
    if (i >= n_pairs) return;
    if (nb32[2 * i + 1] != 0) atomicOr(&g_odd_nonzero, 1);
}

// =====================================================================
// K1: h = x @ pca_w + pca_b. BM=BN=128, BK=16, 256 thr, 8x8 microtile
// via f32x2 (4 row-pairs x 8 cols), double-buffered smem.
// =====================================================================
__global__ void __launch_bounds__(256, 1)
k_gemm_pca(const float* __restrict__ x,
           const float* __restrict__ W,
           const float* __restrict__ bias,
           int n)
{
    __shared__ float As[2][16][128];   // transposed: As[buf][k][m]
    __shared__ float Bs[2][16][128];

    int tid = threadIdx.x;
    int tx = tid & 15;      // n-dir: 8 cols at tx*8
    int ty = tid >> 4;      // m-dir: 8 rows at ty*8
    int row0 = blockIdx.x * 128;

    // per-tile load indices
    int a_r = (tid * 2) >> 2;          // row for A loads (i=0); i=1 is +? (see below)
    // A: idx = tid*2 + i; r = idx>>2, q = (idx&3)*4
    // B: rr = idx>>5, cq = (idx&31)*4

    const int NT = (NFEAT + 15) / 16;  // 32 tiles

    float4 ra[2], rb[2];
    auto load_regs = [&](int kt) {
#pragma unroll
        for (int i = 0; i < 2; i++) {
            int idx = tid * 2 + i;
            int r = idx >> 2;
            int q = (idx & 3) * 4;
            int grow = row0 + r;
            int col = kt + q;
            float4 v = make_float4(0.f, 0.f, 0.f, 0.f);
            if (grow < n && col + 3 < NFEAT)
                v = *(const float4*)(x + (size_t)grow * NFEAT + col);
            ra[i] = v;
            int rr = idx >> 5;
            int cq = (idx & 31) * 4;
            float4 w4 = make_float4(0.f, 0.f, 0.f, 0.f);
            if (kt + rr < NFEAT)
                w4 = *(const float4*)(W + (size_t)(kt + rr) * DFULL + cq);
            rb[i] = w4;
        }
    };
    auto store_smem = [&](int buf) {
#pragma unroll
        for (int i = 0; i < 2; i++) {
            int idx = tid * 2 + i;
            int r = idx >> 2;
            int q = (idx & 3) * 4;
            As[buf][q + 0][r] = ra[i].x; As[buf][q + 1][r] = ra[i].y;
            As[buf][q + 2][r] = ra[i].z; As[buf][q + 3][r] = ra[i].w;
            int rr = idx >> 5;
            int cq = (idx & 31) * 4;
            *(float4*)&Bs[buf][rr][cq] = rb[i];
        }
    };

    u64 acc2[4][8];
#pragma unroll
    for (int rp = 0; rp < 4; rp++)
#pragma unroll
        for (int c = 0; c < 8; c++) acc2[rp][c] = 0ull;

    load_regs(0);
    store_smem(0);
    __syncthreads();

    for (int t = 0; t < NT; t++) {
        int cur = t & 1;
        if (t + 1 < NT) load_regs((t + 1) * 16);

#pragma unroll
        for (int kk = 0; kk < 16; kk++) {
            ulonglong2 a01 = *(ulonglong2*)&As[cur][kk][ty * 8];
            ulonglong2 a23 = *(ulonglong2*)&As[cur][kk][ty * 8 + 4];
            u64 ap[4] = {a01.x, a01.y, a23.x, a23.y};
            float4 b0 = *(float4*)&Bs[cur][kk][tx * 8];
            float4 b1 = *(float4*)&Bs[cur][kk][tx * 8 + 4];
            u64 bd[8];
            bd[0] = pack2(b0.x, b0.x); bd[1] = pack2(b0.y, b0.y);
            bd[2] = pack2(b0.z, b0.z); bd[3] = pack2(b0.w, b0.w);
            bd[4] = pack2(b1.x, b1.x); bd[5] = pack2(b1.y, b1.y);
            bd[6] = pack2(b1.z, b1.z); bd[7] = pack2(b1.w, b1.w);
#pragma unroll
            for (int rp = 0; rp < 4; rp++)
#pragma unroll
                for (int c = 0; c < 8; c++)
                    acc2[rp][c] = fma2(ap[rp], bd[c], acc2[rp][c]);
        }

        if (t + 1 < NT) {
            store_smem(cur ^ 1);
        }
        __syncthreads();
    }

    float bvv[8];
#pragma unroll
    for (int c = 0; c < 8; c++) bvv[c] = bias[tx * 8 + c];
#pragma unroll
    for (int rp = 0; rp < 4; rp++) {
        float lo[8], hi[8];
#pragma unroll
        for (int c = 0; c < 8; c++) unpack2(acc2[rp][c], lo[c], hi[c]);
        int grow = row0 + ty * 8 + rp * 2;
        if (grow < n) {
            float4 o0 = make_float4(lo[0]+bvv[0], lo[1]+bvv[1], lo[2]+bvv[2], lo[3]+bvv[3]);
            float4 o1 = make_float4(lo[4]+bvv[4], lo[5]+bvv[5], lo[6]+bvv[6], lo[7]+bvv[7]);
            *(float4*)(g_h + (size_t)grow * DFULL + tx * 8)     = o0;
            *(float4*)(g_h + (size_t)grow * DFULL + tx * 8 + 4) = o1;
        }
        if (grow + 1 < n) {
            float4 o0 = make_float4(hi[0]+bvv[0], hi[1]+bvv[1], hi[2]+bvv[2], hi[3]+bvv[3]);
            float4 o1 = make_float4(hi[4]+bvv[4], hi[5]+bvv[5], hi[6]+bvv[6], hi[7]+bvv[7]);
            *(float4*)(g_h + (size_t)(grow + 1) * DFULL + tx * 8)     = o0;
            *(float4*)(g_h + (size_t)(grow + 1) * DFULL + tx * 8 + 4) = o1;
        }
    }
}

// =====================================================================
// K2: per-node attention-loss contribution + xn0 = normalize(relu(h))
// =====================================================================
__global__ void k_attn_xn0(const float* __restrict__ ln_g,
                           const float* __restrict__ ln_b,
                           const float* __restrict__ wqs,
                           const float* __restrict__ wks,
                           int n)
{
    __shared__ float sQ[8][128];
    __shared__ float sH[8][128];
    __shared__ float sS[8][64];
    __shared__ float s_wq[256], s_wk[256];
    __shared__ float s_g[16], s_b[16];
    __shared__ float blk_acc;

    int tid = threadIdx.x;
    { s_wq[tid] = wqs[tid]; s_wk[tid] = wks[tid]; }
    if (tid < 16)  { s_g[tid] = ln_g[tid]; s_b[tid] = ln_b[tid]; }
    if (tid == 0)  blk_acc = 0.f;
    __syncthreads();

    int wp = tid >> 5, lane = tid & 31;
    int v = blockIdx.x * 8 + wp;
    if (v < n) {
        int a  = lane >> 2;
        int c0 = (lane & 3) * 4;
        float4 h4 = *(const float4*)(g_h + (size_t)v * DFULL + lane * 4);
        float hv[4] = {h4.x, h4.y, h4.z, h4.w};

        float s1 = hv[0] + hv[1] + hv[2] + hv[3];
        float s2 = hv[0]*hv[0] + hv[1]*hv[1] + hv[2]*hv[2] + hv[3]*hv[3];
        s1 += __shfl_xor_sync(0xffffffffu, s1, 1);
        s1 += __shfl_xor_sync(0xffffffffu, s1, 2);
        s2 += __shfl_xor_sync(0xffffffffu, s2, 1);
        s2 += __shfl_xor_sync(0xffffffffu, s2, 2);
        float mu  = s1 * (1.f / 16.f);
        float var = s2 * (1.f / 16.f) - mu * mu;
        float inv = rsqrtf(var + 1e-6f);
        float qn[4];
#pragma unroll
        for (int i = 0; i < 4; i++)
            qn[i] = (hv[i] - mu) * inv * s_g[c0 + i] + s_b[c0 + i];

#pragma unroll
        for (int i = 0; i < 4; i++) {
            sQ[wp][lane * 4 + i] = qn[i];
            sH[wp][lane * 4 + i] = hv[i];
        }
        __syncwarp();

        float q4[4] = {0.f, 0.f, 0.f, 0.f};
        float k4[4] = {0.f, 0.f, 0.f, 0.f};
#pragma unroll
        for (int j = 0; j < 16; j++) {
            float qa = sQ[wp][a * 16 + j];
            float ha = sH[wp][a * 16 + j];
#pragma unroll
            for (int i = 0; i < 4; i++) {
                q4[i] = fmaf(qa, s_wq[j * 16 + c0 + i], q4[i]);
                k4[i] = fmaf(ha, s_wk[j * 16 + c0 + i], k4[i]);
            }
        }
        __syncwarp();
#pragma unroll
        for (int i = 0; i < 4; i++) {
            sQ[wp][lane * 4 + i] = q4[i];
            sH[wp][lane * 4 + i] = k4[i];
        }
        __syncwarp();

        float sc[2];
#pragma unroll
        for (int r = 0; r < 2; r++) {
            int id = lane * 2 + r;
            int aa = id >> 3, bb = id & 7;
            float s = 0.f;
#pragma unroll
            for (int c = 0; c < 16; c++)
                s = fmaf(sQ[wp][aa * 16 + c], sH[wp][bb * 16 + c], s);
            sc[r] = s * 0.25f;
        }
        sS[wp][lane * 2 + 0] = sc[0];
        sS[wp][lane * 2 + 1] = sc[1];
        __syncwarp();

        float contrib = 0.f;
        if (lane < 8) {
            float mx = -1e30f;
#pragma unroll
            for (int b = 0; b < 8; b++) mx = fmaxf(mx, sS[wp][lane * 8 + b]);
            float sum = 0.f;
#pragma unroll
            for (int b = 0; b < 8; b++) sum += expf(sS[wp][lane * 8 + b] - mx);
            float diag = expf(sS[wp][lane * 8 + lane] - mx) / sum;
            contrib = 1.f - diag;
        }
        contrib += __shfl_xor_sync(0xffffffffu, contrib, 1);
        contrib += __shfl_xor_sync(0xffffffffu, contrib, 2);
        contrib += __shfl_xor_sync(0xffffffffu, contrib, 4);
        if (lane == 0) atomicAdd(&blk_acc, contrib);

        float r4[4];
#pragma unroll
        for (int i = 0; i < 4; i++) r4[i] = fmaxf(hv[i], 0.f);
        float ss = r4[0]*r4[0] + r4[1]*r4[1] + r4[2]*r4[2] + r4[3]*r4[3];
        ss += __shfl_xor_sync(0xffffffffu, ss, 1);
        ss += __shfl_xor_sync(0xffffffffu, ss, 2);
        float scale = 1.f / fmaxf(sqrtf(ss), 1e-12f);
        float4 o = make_float4(r4[0]*scale, r4[1]*scale, r4[2]*scale, r4[3]*scale);
        *(float4*)(g_xn0 + (size_t)v * DFULL + lane * 4) = o;
    }
    __syncthreads();
    if (tid == 0) atomicAdd(&g_attn, blk_acc);
}

// =====================================================================
// K3/K4: dynamic routing, f32x2 + reduce-scatter. 4 nodes/block,
// 2 warps (64 thr) per node. lane = g*8+k. z2[4][8] f32x2 in regs.
// =====================================================================
template <bool LAST>
__global__ void __launch_bounds__(256)
k_routing(const float* __restrict__ xn,
          const int* __restrict__ nb32,
          float* __restrict__ xn_out,
          int n)
{
    __shared__ float x3s [4][128];
    __shared__ float u_s [4][128];
    __shared__ float part[4][2][8][16];

    int t = threadIdx.x;
    int node = t >> 6;
    int l = t & 63;
    int w = (t >> 5) & 1;
    int lane = t & 31;
    int g = lane >> 3;
    int k = lane & 7;

    int v = blockIdx.x * 4 + node;
    bool valid = v < n;
    int vv = valid ? v : (n - 1);
    int st = g_odd_nonzero ? 1 : 2;

    if (l < 32)
        ((float4*)x3s[node])[l] = ((const float4*)(xn + (size_t)vv * DFULL))[l];

    // gather z2[4][8] (f32x2 pairs)
    u64 z2[4][8];
#pragma unroll
    for (int mm = 0; mm < 4; mm++) {
        int m = w * 16 + mm * 4 + g;
        int nbv = nb_at(nb32, (size_t)vv * MNB + m, st);
        if (nbv >= 0) {
            const ulonglong2* src = (const ulonglong2*)(xn + (size_t)nbv * DFULL + k * DD);
#pragma unroll
            for (int q = 0; q < 4; q++) {
                ulonglong2 t2 = src[q];
                z2[mm][q*2]   = t2.x;
                z2[mm][q*2+1] = t2.y;
            }
        } else {
#pragma unroll
            for (int i = 0; i < 8; i++) z2[mm][i] = 0ull;
        }
    }
    __syncthreads();

    int kk2 = l >> 3;          // phase-2 row (0..7)
    int c0  = (l & 7) * 2;     // phase-2 col pair
    bool gb1 = (g & 2) != 0;
    bool gb0 = (g & 1) != 0;
    const u64 c0125 = pack2(0.125f, 0.125f);

    for (int it = 0; it < RIT; it++) {
        u64 acc2[8];
        if (it == 0) {
            // p == 1/8 uniformly
#pragma unroll
            for (int c = 0; c < 8; c++)
                acc2[c] = mul2(add2(add2(z2[0][c], z2[1][c]),
                                    add2(z2[2][c], z2[3][c])), c0125);
        } else {
            // u2 = u row k
            ulonglong2 ua = *(ulonglong2*)&u_s[node][k * 16];
            ulonglong2 ub = *(ulonglong2*)&u_s[node][k * 16 + 4];
            ulonglong2 uc = *(ulonglong2*)&u_s[node][k * 16 + 8];
            ulonglong2 ud = *(ulonglong2*)&u_s[node][k * 16 + 12];
            u64 u2[8] = {ua.x, ua.y, ub.x, ub.y, uc.x, uc.y, ud.x, ud.y};

            float s[4];
#pragma unroll
            for (int mm = 0; mm < 4; mm++) {
                u64 d0 = mul2(z2[mm][0], u2[0]);
                u64 d1 = mul2(z2[mm][1], u2[1]);
                d0 = fma2(z2[mm][2], u2[2], d0);
                d1 = fma2(z2[mm][3], u2[3], d1);
                d0 = fma2(z2[mm][4], u2[4], d0);
                d1 = fma2(z2[mm][5], u2[5], d1);
                d0 = fma2(z2[mm][6], u2[6], d0);
                d1 = fma2(z2[mm][7], u2[7], d1);
                d0 = add2(d0, d1);
                float lo, hi; unpack2(d0, lo, hi);
                s[mm] = lo + hi;
            }

            if (LAST && it == RIT - 1) {
                if (w == 0) {
#pragma unroll
                    for (int mm = 0; mm < 2; mm++) {
                        float bs = s[mm]; int bk = k;
#pragma unroll
                        for (int d = 1; d <= 4; d <<= 1) {
                            float os = __shfl_xor_sync(0xffffffffu, bs, d);
                            int   ok = __shfl_xor_sync(0xffffffffu, bk, d);
                            if (os > bs || (os == bs && ok < bk)) { bs = os; bk = ok; }
                        }
                        int m = mm * 4 + g;
                        if (k == 0 && m < CUTN && valid)
                            g_arg[(size_t)v * CUTN + m] = (unsigned char)bk;
                    }
                }
            }

            // softmax over k (8-lane groups); |s|<=1 so no max-subtract
            float p[4];
#pragma unroll
            for (int mm = 0; mm < 4; mm++) {
                float e = __expf(s[mm]);
                float sum = e;
                sum += __shfl_xor_sync(0xffffffffu, sum, 1);
                sum += __shfl_xor_sync(0xffffffffu, sum, 2);
                sum += __shfl_xor_sync(0xffffffffu, sum, 4);
                p[mm] = e / sum;
            }
            u64 p2[4];
#pragma unroll
            for (int mm = 0; mm < 4; mm++) p2[mm] = pack2(p[mm], p[mm]);
#pragma unroll
            for (int c = 0; c < 8; c++)
                acc2[c] = fma2(p2[0], z2[0][c],
                          fma2(p2[1], z2[1][c],
                          fma2(p2[2], z2[2][c], mul2(p2[3], z2[3][c]))));
        }

        // unpack to scalars
        float acc[16];
#pragma unroll
        for (int c = 0; c < 8; c++) unpack2(acc2[c], acc[2*c], acc[2*c+1]);

        // reduce-scatter over g: stage 1 (xor 16 = g bit1)
        float red[8];
#pragma unroll
        for (int j = 0; j < 8; j++) {
            float keep = gb1 ? acc[8 + j] : acc[j];
            float send = gb1 ? acc[j]     : acc[8 + j];
            red[j] = keep + __shfl_xor_sync(0xffffffffu, send, 16);
        }
        // stage 2 (xor 8 = g bit0)
        float quad[4];
#pragma unroll
        for (int j = 0; j < 4; j++) {
            float keep = gb0 ? red[4 + j] : red[j];
            float send = gb0 ? red[j]     : red[4 + j];
            quad[j] = keep + __shfl_xor_sync(0xffffffffu, send, 8);
        }
        *(float4*)&part[node][w][k][g * 4] =
            make_float4(quad[0], quad[1], quad[2], quad[3]);
        __syncthreads();

        // phase 2: u[k][c] = x3 + part0 + part1 (+ normalize)
        {
            float nu0 = x3s[node][kk2*16 + c0]     + part[node][0][kk2][c0]
                        + part[node][1][kk2][c0];
            float nu1 = x3s[node][kk2*16 + c0 + 1] + part[node][0][kk2][c0+1]
                        + part[node][1][kk2][c0+1];
            if (it < RIT - 1) {
                float ss = nu0*nu0 + nu1*nu1;
                ss += __shfl_xor_sync(0xffffffffu, ss, 1);
                ss += __shfl_xor_sync(0xffffffffu, ss, 2);
                ss += __shfl_xor_sync(0xffffffffu, ss, 4);
                float scale = 1.f / fmaxf(sqrtf(ss), 1e-12f);
                nu0 *= scale; nu1 *= scale;
                u_s[node][kk2*16 + c0]     = nu0;
                u_s[node][kk2*16 + c0 + 1] = nu1;
                __syncthreads();
            } else {
                if (valid) {
                    if (LAST) {
                        g_u[(size_t)v * DFULL + kk2*16 + c0]     = nu0;
                        g_u[(size_t)v * DFULL + kk2*16 + c0 + 1] = nu1;
                    } else {
                        float r0 = fmaxf(nu0, 0.f), r1 = fmaxf(nu1, 0.f);
                        float ss = r0*r0 + r1*r1;
                        ss += __shfl_xor_sync(0xffffffffu, ss, 1);
                        ss += __shfl_xor_sync(0xffffffffu, ss, 2);
                        ss += __shfl_xor_sync(0xffffffffu, ss, 4);
                        float scale = 1.f / fmaxf(sqrtf(ss), 1e-12f);
                        xn_out[(size_t)v * DFULL + kk2*16 + c0]     = r0 * scale;
                        xn_out[(size_t)v * DFULL + kk2*16 + c0 + 1] = r1 * scale;
                    }
                } else if (!LAST) {
                    float ss = 0.f;
                    ss += __shfl_xor_sync(0xffffffffu, ss, 1);
                    ss += __shfl_xor_sync(0xffffffffu, ss, 2);
                    ss += __shfl_xor_sync(0xffffffffu, ss, 4);
                }
            }
        }
    }
}

// =====================================================================
// K5: T[w,:] = sum_{j<5} xn1[nb[w,j], arg[w,j], :]
// =====================================================================
__global__ void k_compute_T(const int* __restrict__ nb32, int n)
{
    int tid = blockIdx.x * blockDim.x + threadIdx.x;
    if (tid >= n * DD) return;
    int w = tid >> 4, c = tid & 15;
    int st = g_odd_nonzero ? 1 : 2;
    float s = 0.f;
#pragma unroll
    for (int j = 0; j < CUTN; j++) {
        int nv = nb_at(nb32, (size_t)w * MNB + j, st);
        if (nv >= 0) {
            int a = g_arg[(size_t)w * CUTN + j];
            s += g_xn1[(size_t)nv * DFULL + a * DD + c];
        }
    }
    g_T[tid] = s;
}

// =====================================================================
// K6: meta + logits + log_softmax + attn scalar
// =====================================================================
__global__ void k_meta_out(const int* __restrict__ nb32,
                           const float* __restrict__ mlp_w,
                           const float* __restrict__ mlp_b,
                           float* __restrict__ out,
                           int n)
{
    __shared__ float s_w[128 * 16];
    __shared__ float s_b[16];
    __shared__ float sM[8][128];

    int tid = threadIdx.x;
    for (int i = tid; i < 2048; i += 256) s_w[i] = mlp_w[i];
    if (tid < 16) s_b[tid] = mlp_b[tid];
    __syncthreads();

    int st = g_odd_nonzero ? 1 : 2;
    int wp = tid >> 5, lane = tid & 31;
    int v = blockIdx.x * 8 + wp;
    if (v < n) {
        int a = lane >> 2;
        float4 acc = *(const float4*)(g_u + (size_t)v * DFULL + lane * 4);
        const float inv25 = 1.f / 25.f;
#pragma unroll
        for (int j = 0; j < CUTN; j++) {
            int nv = nb_at(nb32, (size_t)v * MNB + j, st);
            if (nv >= 0) {
                int aj = g_arg[(size_t)v * CUTN + j];
                if (aj == a) {
                    float4 t4 = *(const float4*)(g_T + (size_t)nv * DD + (lane & 3) * 4);
                    acc.x = fmaf(inv25, t4.x, acc.x);
                    acc.y = fmaf(inv25, t4.y, acc.y);
                    acc.z = fmaf(inv25, t4.z, acc.z);
                    acc.w = fmaf(inv25, t4.w, acc.w);
                }
            }
        }
        acc.x = fmaxf(acc.x, 0.f); acc.y = fmaxf(acc.y, 0.f);
        acc.z = fmaxf(acc.z, 0.f); acc.w = fmaxf(acc.w, 0.f);
        *(float4*)&sM[wp][lane * 4] = acc;
        __syncwarp();

        float logit = 0.f;
        if (lane < 16) {
            logit = s_b[lane];
            for (int f = 0; f < 128; f++)
                logit = fmaf(sM[wp][f], s_w[f * 16 + lane], logit);
            out[(size_t)n * 16 + 1 + (size_t)v * 16 + lane] = logit;
        }
        float mx = (lane < 16) ? logit : -1e30f;
        mx = fmaxf(mx, __shfl_xor_sync(0xffffffffu, mx, 1));
        mx = fmaxf(mx, __shfl_xor_sync(0xffffffffu, mx, 2));
        mx = fmaxf(mx, __shfl_xor_sync(0xffffffffu, mx, 4));
        mx = fmaxf(mx, __shfl_xor_sync(0xffffffffu, mx, 8));
        float e = (lane < 16) ? expf(logit - mx) : 0.f;
        float sum = e;
        sum += __shfl_xor_sync(0xffffffffu, sum, 1);
        sum += __shfl_xor_sync(0xffffffffu, sum, 2);
        sum += __shfl_xor_sync(0xffffffffu, sum, 4);
        sum += __shfl_xor_sync(0xffffffffu, sum, 8);
        if (lane < 16)
            out[(size_t)v * 16 + lane] = (logit - mx) - logf(sum);
    }
    if (blockIdx.x == 0 && tid == 0)
        out[(size_t)n * 16] = g_attn / (56.f * (float)n);
}

// =====================================================================
extern "C" void kernel_launch(void* const* d_in, const int* in_sizes, int n_in,
                              void* d_out, int out_size)
{
    const float* x     = (const float*)d_in[0];
    const int*   nb32  = (const int*)d_in[1];
    const float* pca_w = (const float*)d_in[2];
    const float* pca_b = (const float*)d_in[3];
    const float* ln_g  = (const float*)d_in[4];
    const float* ln_b  = (const float*)d_in[5];
    const float* w_qs  = (const float*)d_in[6];
    const float* w_ks  = (const float*)d_in[7];
    const float* mlp_w = (const float*)d_in[8];
    const float* mlp_b = (const float*)d_in[9];
    float* out = (float*)d_out;

    int n = in_sizes[0] / NFEAT;   // 20000
    int n_nb = in_sizes[1];

    float* p_xn0; cudaGetSymbolAddress((void**)&p_xn0, g_xn0);
    float* p_xn1; cudaGetSymbolAddress((void**)&p_xn1, g_xn1);

    k_detect_nb_init<<<1, 1>>>();
    k_detect_nb<<<(n_nb / 2 + 255) / 256, 256>>>(nb32, n_nb / 2);
    k_gemm_pca<<<(n + 127) / 128, 256>>>(x, pca_w, pca_b, n);
    k_attn_xn0<<<(n + 7) / 8, 256>>>(ln_g, ln_b, w_qs, w_ks, n);
    k_routing<false><<<(n + 3) / 4, 256>>>(p_xn0, nb32, p_xn1, n);
    k_routing<true ><<<(n + 3) / 4, 256>>>(p_xn1, nb32, nullptr, n);
    k_compute_T<<<(n * DD + 255) / 256, 256>>>(nb32, n);
    k_meta_out<<<(n + 7) / 8, 256>>>(nb32, mlp_w, mlp_b, out, n);
}

// round 5
// speedup vs baseline: 2.3127x; 1.2348x over previous
#include <cuda_runtime.h>
#include <math.h>

#define NFEAT 500
#define DFULL 128
#define NCAP  8
#define DD    16
#define MNB   32
#define RIT   6
#define CUTN  5
#define NMAX  20000
#define NCLASS 16

typedef unsigned long long u64;

// ---- packed f32x2 helpers (sm_100+) ----
__device__ __forceinline__ u64 pack2(float lo, float hi) {
    u64 r; asm("mov.b64 %0, {%1, %2};" : "=l"(r) : "f"(lo), "f"(hi)); return r;
}
__device__ __forceinline__ void unpack2(u64 v, float& lo, float& hi) {
    asm("mov.b64 {%0, %1}, %2;" : "=f"(lo), "=f"(hi) : "l"(v));
}
__device__ __forceinline__ u64 fma2(u64 a, u64 b, u64 c) {
    u64 d; asm("fma.rn.f32x2 %0, %1, %2, %3;" : "=l"(d) : "l"(a), "l"(b), "l"(c)); return d;
}
__device__ __forceinline__ u64 add2(u64 a, u64 b) {
    u64 d; asm("add.rn.f32x2 %0, %1, %2;" : "=l"(d) : "l"(a), "l"(b)); return d;
}
__device__ __forceinline__ u64 mul2(u64 a, u64 b) {
    u64 d; asm("mul.rn.f32x2 %0, %1, %2;" : "=l"(d) : "l"(a), "l"(b)); return d;
}

// ---- scratch ----
__device__ float g_h  [NMAX * DFULL];
__device__ float g_xn0[NMAX * DFULL];
__device__ float g_xn1[NMAX * DFULL];
__device__ float g_u  [NMAX * DFULL];
__device__ float g_T  [NMAX * DD];
__device__ unsigned char g_arg[NMAX * CUTN];
__device__ float g_attn;
__device__ int   g_odd_nonzero = 0;  // monotone 0->1; set each run before consumers

// =====================================================================
// K0: detect nb dtype (single kernel; static init is safe: value is
// monotone and set before any consumer in every run).
// =====================================================================
__global__ void k_detect_nb(const int* __restrict__ nb32, int n_pairs)
{
    int i = blockIdx.x * blockDim.x + threadIdx.x;
    if (i >= n_pairs) return;
    if (nb32[2 * i + 1] != 0) atomicOr(&g_odd_nonzero, 1);
}

// =====================================================================
// K1: h = x @ pca_w + pca_b. BM=64, BN=128, BK=16, 256 thr.
// acc = 4 rows x 4 col-pairs (f32x2), B read directly as pairs,
// A dup-packed. Double-buffered smem.
// =====================================================================
__global__ void __launch_bounds__(256, 2)
k_gemm_pca(const float* __restrict__ x,
           const float* __restrict__ W,
           const float* __restrict__ bias,
           int n)
{
    __shared__ float As[2][16][72];    // transposed, padded (bank-safe)
    __shared__ float Bs[2][16][128];

    int tid = threadIdx.x;
    int tx = tid & 15;       // col group: cols tx*8 (4 pairs)
    int ty = tid >> 4;       // rows ty*4 .. ty*4+3
    int row0 = blockIdx.x * 64;

    if (blockIdx.x == 0 && tid == 0) g_attn = 0.f;

    const int NT = (NFEAT + 15) / 16;  // 32

    float4 ra, rb[2];
    auto load_regs = [&](int kt) {
        {
            int r = tid >> 2;
            int q = (tid & 3) * 4;
            int grow = row0 + r;
            int col = kt + q;
            float4 v = make_float4(0.f, 0.f, 0.f, 0.f);
            if (grow < n && col + 3 < NFEAT)
                v = *(const float4*)(x + (size_t)grow * NFEAT + col);
            ra = v;
        }
#pragma unroll
        for (int i = 0; i < 2; i++) {
            int idx = tid * 2 + i;
            int rr = idx >> 5;
            int cq = (idx & 31) * 4;
            float4 w4 = make_float4(0.f, 0.f, 0.f, 0.f);
            if (kt + rr < NFEAT)
                w4 = *(const float4*)(W + (size_t)(kt + rr) * DFULL + cq);
            rb[i] = w4;
        }
    };
    auto store_smem = [&](int buf) {
        {
            int r = tid >> 2;
            int q = (tid & 3) * 4;
            As[buf][q + 0][r] = ra.x; As[buf][q + 1][r] = ra.y;
            As[buf][q + 2][r] = ra.z; As[buf][q + 3][r] = ra.w;
        }
#pragma unroll
        for (int i = 0; i < 2; i++) {
            int idx = tid * 2 + i;
            int rr = idx >> 5;
            int cq = (idx & 31) * 4;
            *(float4*)&Bs[buf][rr][cq] = rb[i];
        }
    };

    u64 acc2[4][4];
#pragma unroll
    for (int r = 0; r < 4; r++)
#pragma unroll
        for (int cp = 0; cp < 4; cp++) acc2[r][cp] = 0ull;

    load_regs(0);
    store_smem(0);
    __syncthreads();

    for (int t = 0; t < NT; t++) {
        int cur = t & 1;
        if (t + 1 < NT) load_regs((t + 1) * 16);

#pragma unroll
        for (int kk = 0; kk < 16; kk++) {
            float4 a4 = *(float4*)&As[cur][kk][ty * 4];
            u64 ad[4];
            ad[0] = pack2(a4.x, a4.x); ad[1] = pack2(a4.y, a4.y);
            ad[2] = pack2(a4.z, a4.z); ad[3] = pack2(a4.w, a4.w);
            ulonglong2 bp0 = *(ulonglong2*)&Bs[cur][kk][tx * 8];
            ulonglong2 bp1 = *(ulonglong2*)&Bs[cur][kk][tx * 8 + 4];
            u64 bd[4] = {bp0.x, bp0.y, bp1.x, bp1.y};
#pragma unroll
            for (int r = 0; r < 4; r++)
#pragma unroll
                for (int cp = 0; cp < 4; cp++)
                    acc2[r][cp] = fma2(ad[r], bd[cp], acc2[r][cp]);
        }

        if (t + 1 < NT) store_smem(cur ^ 1);
        __syncthreads();
    }

    float4 b0 = *(const float4*)(bias + tx * 8);
    float4 b1 = *(const float4*)(bias + tx * 8 + 4);
    u64 bb[4] = {pack2(b0.x, b0.y), pack2(b0.z, b0.w),
                 pack2(b1.x, b1.y), pack2(b1.z, b1.w)};
#pragma unroll
    for (int r = 0; r < 4; r++) {
        int grow = row0 + ty * 4 + r;
        if (grow < n) {
            ulonglong2 o0, o1;
            o0.x = add2(acc2[r][0], bb[0]); o0.y = add2(acc2[r][1], bb[1]);
            o1.x = add2(acc2[r][2], bb[2]); o1.y = add2(acc2[r][3], bb[3]);
            *(ulonglong2*)(g_h + (size_t)grow * DFULL + tx * 8)     = o0;
            *(ulonglong2*)(g_h + (size_t)grow * DFULL + tx * 8 + 4) = o1;
        }
    }
}

// =====================================================================
// K2: attention loss + xn0 = normalize(relu(h))  (unchanged, passing)
// =====================================================================
__global__ void k_attn_xn0(const float* __restrict__ ln_g,
                           const float* __restrict__ ln_b,
                           const float* __restrict__ wqs,
                           const float* __restrict__ wks,
                           int n)
{
    __shared__ float sQ[8][128];
    __shared__ float sH[8][128];
    __shared__ float sS[8][64];
    __shared__ float s_wq[256], s_wk[256];
    __shared__ float s_g[16], s_b[16];
    __shared__ float blk_acc;

    int tid = threadIdx.x;
    { s_wq[tid] = wqs[tid]; s_wk[tid] = wks[tid]; }
    if (tid < 16)  { s_g[tid] = ln_g[tid]; s_b[tid] = ln_b[tid]; }
    if (tid == 0)  blk_acc = 0.f;
    __syncthreads();

    int wp = tid >> 5, lane = tid & 31;
    int v = blockIdx.x * 8 + wp;
    if (v < n) {
        int a  = lane >> 2;
        int c0 = (lane & 3) * 4;
        float4 h4 = *(const float4*)(g_h + (size_t)v * DFULL + lane * 4);
        float hv[4] = {h4.x, h4.y, h4.z, h4.w};

        float s1 = hv[0] + hv[1] + hv[2] + hv[3];
        float s2 = hv[0]*hv[0] + hv[1]*hv[1] + hv[2]*hv[2] + hv[3]*hv[3];
        s1 += __shfl_xor_sync(0xffffffffu, s1, 1);
        s1 += __shfl_xor_sync(0xffffffffu, s1, 2);
        s2 += __shfl_xor_sync(0xffffffffu, s2, 1);
        s2 += __shfl_xor_sync(0xffffffffu, s2, 2);
        float mu  = s1 * (1.f / 16.f);
        float var = s2 * (1.f / 16.f) - mu * mu;
        float inv = rsqrtf(var + 1e-6f);
        float qn[4];
#pragma unroll
        for (int i = 0; i < 4; i++)
            qn[i] = (hv[i] - mu) * inv * s_g[c0 + i] + s_b[c0 + i];

#pragma unroll
        for (int i = 0; i < 4; i++) {
            sQ[wp][lane * 4 + i] = qn[i];
            sH[wp][lane * 4 + i] = hv[i];
        }
        __syncwarp();

        float q4[4] = {0.f, 0.f, 0.f, 0.f};
        float k4[4] = {0.f, 0.f, 0.f, 0.f};
#pragma unroll
        for (int j = 0; j < 16; j++) {
            float qa = sQ[wp][a * 16 + j];
            float ha = sH[wp][a * 16 + j];
#pragma unroll
            for (int i = 0; i < 4; i++) {
                q4[i] = fmaf(qa, s_wq[j * 16 + c0 + i], q4[i]);
                k4[i] = fmaf(ha, s_wk[j * 16 + c0 + i], k4[i]);
            }
        }
        __syncwarp();
#pragma unroll
        for (int i = 0; i < 4; i++) {
            sQ[wp][lane * 4 + i] = q4[i];
            sH[wp][lane * 4 + i] = k4[i];
        }
        __syncwarp();

        float sc[2];
#pragma unroll
        for (int r = 0; r < 2; r++) {
            int id = lane * 2 + r;
            int aa = id >> 3, bb = id & 7;
            float s = 0.f;
#pragma unroll
            for (int c = 0; c < 16; c++)
                s = fmaf(sQ[wp][aa * 16 + c], sH[wp][bb * 16 + c], s);
            sc[r] = s * 0.25f;
        }
        sS[wp][lane * 2 + 0] = sc[0];
        sS[wp][lane * 2 + 1] = sc[1];
        __syncwarp();

        float contrib = 0.f;
        if (lane < 8) {
            float mx = -1e30f;
#pragma unroll
            for (int b = 0; b < 8; b++) mx = fmaxf(mx, sS[wp][lane * 8 + b]);
            float sum = 0.f;
#pragma unroll
            for (int b = 0; b < 8; b++) sum += expf(sS[wp][lane * 8 + b] - mx);
            float diag = expf(sS[wp][lane * 8 + lane] - mx) / sum;
            contrib = 1.f - diag;
        }
        contrib += __shfl_xor_sync(0xffffffffu, contrib, 1);
        contrib += __shfl_xor_sync(0xffffffffu, contrib, 2);
        contrib += __shfl_xor_sync(0xffffffffu, contrib, 4);
        if (lane == 0) atomicAdd(&blk_acc, contrib);

        float r4[4];
#pragma unroll
        for (int i = 0; i < 4; i++) r4[i] = fmaxf(hv[i], 0.f);
        float ss = r4[0]*r4[0] + r4[1]*r4[1] + r4[2]*r4[2] + r4[3]*r4[3];
        ss += __shfl_xor_sync(0xffffffffu, ss, 1);
        ss += __shfl_xor_sync(0xffffffffu, ss, 2);
        float scale = 1.f / fmaxf(sqrtf(ss), 1e-12f);
        float4 o = make_float4(r4[0]*scale, r4[1]*scale, r4[2]*scale, r4[3]*scale);
        *(float4*)(g_xn0 + (size_t)v * DFULL + lane * 4) = o;
    }
    __syncthreads();
    if (tid == 0) atomicAdd(&g_attn, blk_acc);
}

// =====================================================================
// K3/K4: routing, permuted-quad dataflow. 2 nodes per 128-thr block,
// 2 warps per node. lane=(g,k). Per-lane c-order = quads [g,g^1,g^2,g^3]
// -> all reduce-scatter / all-gather stages are "keep-low, send-high"
// (no SELs). u row rebuilt in regs (no phase-2); normalization folded
// into next iteration's dot via rsqrt(u.u). One barrier per iter.
// =====================================================================
template <bool LAST>
__global__ void __launch_bounds__(128)
k_routing(const float* __restrict__ xn,
          const int* __restrict__ nb32,
          float* __restrict__ xn_out,
          int n)
{
    __shared__ float part[2][2][2][8][16];   // [buf][node][w][k][c]

    int t = threadIdx.x;
    int node = t >> 6;
    int w = (t >> 5) & 1;
    int lane = t & 31;
    int g = lane >> 3;
    int k = lane & 7;

    int v = blockIdx.x * 2 + node;
    bool valid = v < n;
    int vv = valid ? v : (n - 1);
    int st = g_odd_nonzero ? 1 : 2;

    // x3: natural quad g of row k
    float4 x3q4 = *(const float4*)(xn + (size_t)vv * DFULL + k * DD + g * 4);
    float x3q[4] = {x3q4.x, x3q4.y, x3q4.z, x3q4.w};

    // gather z for 4 neighbors, quads permuted [g, g^1, g^2, g^3]
    u64 z2[4][8];
#pragma unroll
    for (int mm = 0; mm < 4; mm++) {
        int m = w * 16 + mm * 4 + g;
        int nbv = nb32[((size_t)vv * MNB + m) * (size_t)st];
        if (nbv >= 0) {
            const float* base = xn + (size_t)nbv * DFULL + k * DD;
#pragma unroll
            for (int q = 0; q < 4; q++) {
                int qg = g ^ q;
                float4 t4 = *(const float4*)(base + qg * 4);
                z2[mm][q * 2]     = pack2(t4.x, t4.y);
                z2[mm][q * 2 + 1] = pack2(t4.z, t4.w);
            }
        } else {
#pragma unroll
            for (int i = 0; i < 8; i++) z2[mm][i] = 0ull;
        }
    }

    u64 u2[8];                 // RAW u row k (permuted); valid from it>=1
#pragma unroll
    for (int i = 0; i < 8; i++) u2[i] = 0ull;

    const u64 c0125 = pack2(0.125f, 0.125f);

    for (int it = 0; it < RIT; it++) {
        u64 acc2[8];
        if (it == 0) {
#pragma unroll
            for (int c = 0; c < 8; c++)
                acc2[c] = mul2(add2(add2(z2[0][c], z2[1][c]),
                                    add2(z2[2][c], z2[3][c])), c0125);
        } else {
            // per-k inverse norm of raw u
            u64 d = mul2(u2[0], u2[0]);
#pragma unroll
            for (int i = 1; i < 8; i++) d = fma2(u2[i], u2[i], d);
            float nl, nh; unpack2(d, nl, nh);
            float invn = rsqrtf(fmaxf(nl + nh, 1e-24f));

            float s[4];
#pragma unroll
            for (int mm = 0; mm < 4; mm++) {
                u64 d0 = mul2(z2[mm][0], u2[0]);
                u64 d1 = mul2(z2[mm][1], u2[1]);
                d0 = fma2(z2[mm][2], u2[2], d0);
                d1 = fma2(z2[mm][3], u2[3], d1);
                d0 = fma2(z2[mm][4], u2[4], d0);
                d1 = fma2(z2[mm][5], u2[5], d1);
                d0 = fma2(z2[mm][6], u2[6], d0);
                d1 = fma2(z2[mm][7], u2[7], d1);
                d0 = add2(d0, d1);
                float lo, hi; unpack2(d0, lo, hi);
                s[mm] = (lo + hi) * invn;
            }

            if (LAST && it == RIT - 1 && w == 0) {
#pragma unroll
                for (int mm = 0; mm < 2; mm++) {
                    float bs = s[mm]; int bk = k;
#pragma unroll
                    for (int d2 = 1; d2 <= 4; d2 <<= 1) {
                        float os = __shfl_xor_sync(0xffffffffu, bs, d2);
                        int   ok = __shfl_xor_sync(0xffffffffu, bk, d2);
                        if (os > bs || (os == bs && ok < bk)) { bs = os; bk = ok; }
                    }
                    int m = mm * 4 + g;
                    if (k == 0 && m < CUTN && valid)
                        g_arg[(size_t)v * CUTN + m] = (unsigned char)bk;
                }
            }

            // softmax over k (|s|<=1, no max-subtract needed)
            float p[4];
#pragma unroll
            for (int mm = 0; mm < 4; mm++) {
                float e = __expf(s[mm]);
                float sum = e;
                sum += __shfl_xor_sync(0xffffffffu, sum, 1);
                sum += __shfl_xor_sync(0xffffffffu, sum, 2);
                sum += __shfl_xor_sync(0xffffffffu, sum, 4);
                p[mm] = __fdividef(e, sum);
            }
            u64 p2[4];
#pragma unroll
            for (int mm = 0; mm < 4; mm++) p2[mm] = pack2(p[mm], p[mm]);
#pragma unroll
            for (int c = 0; c < 8; c++)
                acc2[c] = fma2(p2[0], z2[0][c],
                          fma2(p2[1], z2[1][c],
                          fma2(p2[2], z2[2][c], mul2(p2[3], z2[3][c]))));
        }

        float acc[16];
#pragma unroll
        for (int c = 0; c < 8; c++) unpack2(acc2[c], acc[2*c], acc[2*c+1]);

        // reduce-scatter over g: keep-low/send-high both stages (permuted!)
        float red[8];
#pragma unroll
        for (int j = 0; j < 8; j++)
            red[j] = acc[j] + __shfl_xor_sync(0xffffffffu, acc[8 + j], 16);
        float quad[4];
#pragma unroll
        for (int j = 0; j < 4; j++)
            quad[j] = red[j] + __shfl_xor_sync(0xffffffffu, red[4 + j], 8);

        int buf = it & 1;
        *(float4*)&part[buf][node][w][k][g * 4] =
            make_float4(quad[0], quad[1], quad[2], quad[3]);
        __syncthreads();

        float4 o4 = *(float4*)&part[buf][node][1 - w][k][g * 4];
        float oq[4] = {quad[0] + o4.x + x3q[0], quad[1] + o4.y + x3q[1],
                       quad[2] + o4.z + x3q[2], quad[3] + o4.w + x3q[3]};

        if (it == RIT - 1) {
            if (valid && w == 0) {
                if (LAST) {
                    *(float4*)(g_u + (size_t)v * DFULL + k * DD + g * 4) =
                        make_float4(oq[0], oq[1], oq[2], oq[3]);
                } else {
                    float r0 = fmaxf(oq[0], 0.f), r1 = fmaxf(oq[1], 0.f);
                    float r2 = fmaxf(oq[2], 0.f), r3 = fmaxf(oq[3], 0.f);
                    float ssr = r0*r0 + r1*r1 + r2*r2 + r3*r3;
                    ssr += __shfl_xor_sync(0xffffffffu, ssr, 8);
                    ssr += __shfl_xor_sync(0xffffffffu, ssr, 16);
                    float sc = rsqrtf(fmaxf(ssr, 1e-24f));
                    *(float4*)(xn_out + (size_t)v * DFULL + k * DD + g * 4) =
                        make_float4(r0*sc, r1*sc, r2*sc, r3*sc);
                }
            }
        } else {
            // all-gather raw u row into regs (quad order [g,g^1,g^2,g^3])
            float h8[8], f16[16];
#pragma unroll
            for (int j = 0; j < 4; j++) {
                h8[j] = oq[j];
                h8[4 + j] = __shfl_xor_sync(0xffffffffu, oq[j], 8);
            }
#pragma unroll
            for (int j = 0; j < 8; j++) {
                f16[j] = h8[j];
                f16[8 + j] = __shfl_xor_sync(0xffffffffu, h8[j], 16);
            }
#pragma unroll
            for (int i = 0; i < 8; i++)
                u2[i] = pack2(f16[2*i], f16[2*i + 1]);
        }
        // no second barrier: part is double-buffered; writes to this buffer
        // recur only after the NEXT barrier, past all reads.
    }
}

// =====================================================================
// K5: T[w,:] = sum_{j<5} xn1[nb[w,j], arg[w,j], :]
// =====================================================================
__global__ void k_compute_T(const int* __restrict__ nb32, int n)
{
    int tid = blockIdx.x * blockDim.x + threadIdx.x;
    if (tid >= n * DD) return;
    int w = tid >> 4, c = tid & 15;
    int st = g_odd_nonzero ? 1 : 2;
    float s = 0.f;
#pragma unroll
    for (int j = 0; j < CUTN; j++) {
        int nv = nb32[((size_t)w * MNB + j) * (size_t)st];
        if (nv >= 0) {
            int a = g_arg[(size_t)w * CUTN + j];
            s += g_xn1[(size_t)nv * DFULL + a * DD + c];
        }
    }
    g_T[tid] = s;
}

// =====================================================================
// K6: meta + logits + log_softmax + attn scalar
// =====================================================================
__global__ void k_meta_out(const int* __restrict__ nb32,
                           const float* __restrict__ mlp_w,
                           const float* __restrict__ mlp_b,
                           float* __restrict__ out,
                           int n)
{
    __shared__ float s_w[128 * 16];
    __shared__ float s_b[16];
    __shared__ float sM[8][128];

    int tid = threadIdx.x;
    for (int i = tid; i < 2048; i += 256) s_w[i] = mlp_w[i];
    if (tid < 16) s_b[tid] = mlp_b[tid];
    __syncthreads();

    int st = g_odd_nonzero ? 1 : 2;
    int wp = tid >> 5, lane = tid & 31;
    int v = blockIdx.x * 8 + wp;
    if (v < n) {
        int a = lane >> 2;
        float4 acc = *(const float4*)(g_u + (size_t)v * DFULL + lane * 4);
        const float inv25 = 1.f / 25.f;
#pragma unroll
        for (int j = 0; j < CUTN; j++) {
            int nv = nb32[((size_t)v * MNB + j) * (size_t)st];
            if (nv >= 0) {
                int aj = g_arg[(size_t)v * CUTN + j];
                if (aj == a) {
                    float4 t4 = *(const float4*)(g_T + (size_t)nv * DD + (lane & 3) * 4);
                    acc.x = fmaf(inv25, t4.x, acc.x);
                    acc.y = fmaf(inv25, t4.y, acc.y);
                    acc.z = fmaf(inv25, t4.z, acc.z);
                    acc.w = fmaf(inv25, t4.w, acc.w);
                }
            }
        }
        acc.x = fmaxf(acc.x, 0.f); acc.y = fmaxf(acc.y, 0.f);
        acc.z = fmaxf(acc.z, 0.f); acc.w = fmaxf(acc.w, 0.f);
        *(float4*)&sM[wp][lane * 4] = acc;
        __syncwarp();

        float logit = 0.f;
        if (lane < 16) {
            logit = s_b[lane];
            for (int f = 0; f < 128; f++)
                logit = fmaf(sM[wp][f], s_w[f * 16 + lane], logit);
            out[(size_t)n * 16 + 1 + (size_t)v * 16 + lane] = logit;
        }
        float mx = (lane < 16) ? logit : -1e30f;
        mx = fmaxf(mx, __shfl_xor_sync(0xffffffffu, mx, 1));
        mx = fmaxf(mx, __shfl_xor_sync(0xffffffffu, mx, 2));
        mx = fmaxf(mx, __shfl_xor_sync(0xffffffffu, mx, 4));
        mx = fmaxf(mx, __shfl_xor_sync(0xffffffffu, mx, 8));
        float e = (lane < 16) ? expf(logit - mx) : 0.f;
        float sum = e;
        sum += __shfl_xor_sync(0xffffffffu, sum, 1);
        sum += __shfl_xor_sync(0xffffffffu, sum, 2);
        sum += __shfl_xor_sync(0xffffffffu, sum, 4);
        sum += __shfl_xor_sync(0xffffffffu, sum, 8);
        if (lane < 16)
            out[(size_t)v * 16 + lane] = (logit - mx) - logf(sum);
    }
    if (blockIdx.x == 0 && tid == 0)
        out[(size_t)n * 16] = g_attn / (56.f * (float)n);
}

// =====================================================================
extern "C" void kernel_launch(void* const* d_in, const int* in_sizes, int n_in,
                              void* d_out, int out_size)
{
    const float* x     = (const float*)d_in[0];
    const int*   nb32  = (const int*)d_in[1];
    const float* pca_w = (const float*)d_in[2];
    const float* pca_b = (const float*)d_in[3];
    const float* ln_g  = (const float*)d_in[4];
    const float* ln_b  = (const float*)d_in[5];
    const float* w_qs  = (const float*)d_in[6];
    const float* w_ks  = (const float*)d_in[7];
    const float* mlp_w = (const float*)d_in[8];
    const float* mlp_b = (const float*)d_in[9];
    float* out = (float*)d_out;

    int n = in_sizes[0] / NFEAT;   // 20000
    int n_nb = in_sizes[1];

    float* p_xn0; cudaGetSymbolAddress((void**)&p_xn0, g_xn0);
    float* p_xn1; cudaGetSymbolAddress((void**)&p_xn1, g_xn1);

    k_detect_nb<<<(n_nb / 2 + 255) / 256, 256>>>(nb32, n_nb / 2);
    k_gemm_pca<<<(n + 63) / 64, 256>>>(x, pca_w, pca_b, n);
    k_attn_xn0<<<(n + 7) / 8, 256>>>(ln_g, ln_b, w_qs, w_ks, n);
    k_routing<false><<<(n + 1) / 2, 128>>>(p_xn0, nb32, p_xn1, n);
    k_routing<true ><<<(n + 1) / 2, 128>>>(p_xn1, nb32, nullptr, n);
    k_compute_T<<<(n * DD + 255) / 256, 256>>>(nb32, n);
    k_meta_out<<<(n + 7) / 8, 256>>>(nb32, mlp_w, mlp_b, out, n);
}